// round 10
// baseline (speedup 1.0000x reference)
#include <cuda_runtime.h>
#include <cstdint>

// SpectralWindowPreprocessor: out[b,c,j,h,w] = x[b, reflect(c+j-3), h, w]
// B=4, C=31, J=7, H=W=512, reflect padding (mask all-ones).
//
// R7: gather -> SCATTER inversion. Under reflect padding every input channel
// t is consumed by exactly 7 output (c,j) planes. Each thread reads one chunk
// of input ONCE (streaming, no reuse) and writes it to its 7 destination
// planes. This cuts L2 read traffic 7x (total LTS traffic 1.8GB -> 1.04GB),
// leaving the LTS/DRAM path serving only the mandatory 910MB write +
// 130MB read.

static constexpr int C       = 31;
static constexpr int J       = 7;           // 2*3 + 1
static constexpr int HW_VEC  = 65536;       // 512*512/4 float4s per plane
static constexpr int B       = 4;
static constexpr int TPB     = 256;
static constexpr int VPT     = 4;           // float4s per thread (64 B)

// ---- compile-time consumer table: for each input channel t, the 7 output
// ---- plane offsets (c*J + j) that read it.
struct DestTab { int d[C][J]; };

__host__ __device__ constexpr DestTab make_tab() {
    DestTab tb{};
    int cnt[C] = {};
    for (int c = 0; c < C; ++c) {
        for (int j = 0; j < J; ++j) {
            int t = c + j - 3;
            if (t < 0)       t = -t - 1;          // reflect low
            else if (t >= C) t = 2 * C - t - 1;   // reflect high
            tb.d[t][cnt[t]++] = c * J + j;
        }
    }
    return tb;
}

__constant__ DestTab kTab = make_tab();

__global__ __launch_bounds__(TPB)
void spectral_window_scatter_kernel(const float4* __restrict__ x,
                                    float4* __restrict__ out) {
    // blockIdx.y = input plane id in [0, B*C): b*C + t
    const int iplane = blockIdx.y;
    const int t      = iplane % C;
    const int b      = iplane / C;
    const int base   = (blockIdx.x * TPB) * VPT + threadIdx.x;

    const float4* src = x + (size_t)iplane * HW_VEC + base;

    // One streaming read of 4 independent float4s (no reuse anywhere).
    float4 v0 = __ldcs(src + 0 * TPB);
    float4 v1 = __ldcs(src + 1 * TPB);
    float4 v2 = __ldcs(src + 2 * TPB);
    float4 v3 = __ldcs(src + 3 * TPB);

    // Scatter to the 7 consumer output planes (uniform per block -> LDC).
    const size_t bbase = (size_t)b * (C * J) * HW_VEC + base;
#pragma unroll
    for (int k = 0; k < J; ++k) {
        float4* dst = out + bbase + (size_t)kTab.d[t][k] * HW_VEC;
        __stcs(dst + 0 * TPB, v0);
        __stcs(dst + 1 * TPB, v1);
        __stcs(dst + 2 * TPB, v2);
        __stcs(dst + 3 * TPB, v3);
    }
}

extern "C" void kernel_launch(void* const* d_in, const int* in_sizes, int n_in,
                              void* d_out, int out_size) {
    const float4* x   = (const float4*)d_in[0];
    float4*       out = (float4*)d_out;

    dim3 grid(HW_VEC / (TPB * VPT), B * C, 1);   // (64, 124)
    spectral_window_scatter_kernel<<<grid, TPB>>>(x, out);
}